// round 7
// baseline (speedup 1.0000x reference)
#include <cuda_runtime.h>
#include <cuda_fp16.h>
#include <cstdint>

#define USER_N 100000
#define ITEM_N 200000
#define NN     (USER_N + ITEM_N)   // 300000
#define D      64
#define E_NUM  4800000

#define SCAN_BS 512
#define SCAN_NB ((NN + SCAN_BS - 1) / SCAN_BS)   // 586

// ---- static device scratch ----
__device__ __half g_hA[(size_t)NN * D];   // fp16 ping
__device__ __half g_hB[(size_t)NN * D];   // fp16 pong
__device__ int2   g_cv[E_NUM];            // packed (col, val-bits) in CSR order
__device__ int    g_counts[NN];
__device__ int    g_offsets[NN];
__device__ int    g_cursor[NN];
__device__ int    g_blockSums[SCAN_NB];

// ---------------------------------------------------------------------------
// init: out = concat(u,i) (fp32 acc layer-0 term); hA = fp16(concat); counts=0
// ---------------------------------------------------------------------------
__global__ void init_kernel(const float4* __restrict__ u,
                            const float4* __restrict__ i,
                            float4* __restrict__ out,
                            uint2* __restrict__ hA,     // 4 halves per slot
                            int* __restrict__ counts) {
    const unsigned total4 = NN * D / 4;
    const unsigned usplit = USER_N * D / 4;
    unsigned idx = blockIdx.x * blockDim.x + threadIdx.x;
    if (idx < (unsigned)NN) counts[idx] = 0;
    if (idx >= total4) return;
    float4 v = (idx < usplit) ? u[idx] : i[idx - usplit];
    out[idx] = v;
    half2 h0 = __floats2half2_rn(v.x, v.y);
    half2 h1 = __floats2half2_rn(v.z, v.w);
    uint2 packed;
    packed.x = *reinterpret_cast<unsigned*>(&h0);
    packed.y = *reinterpret_cast<unsigned*>(&h1);
    hA[idx] = packed;
}

__global__ void hist_kernel(const int* __restrict__ rows, int* __restrict__ counts) {
    unsigned e = blockIdx.x * blockDim.x + threadIdx.x;
    if (e >= E_NUM) return;
    atomicAdd(counts + __ldg(rows + e), 1);
}

// ---- 3-kernel exclusive scan of counts -> offsets ----
__global__ void scan1_kernel(const int* __restrict__ counts,
                             int* __restrict__ offsets,
                             int* __restrict__ blockSums) {
    __shared__ int sh[SCAN_BS];
    int t = threadIdx.x;
    int i = blockIdx.x * SCAN_BS + t;
    int v = (i < NN) ? counts[i] : 0;
    sh[t] = v;
    __syncthreads();
    for (int ofs = 1; ofs < SCAN_BS; ofs <<= 1) {
        int add = (t >= ofs) ? sh[t - ofs] : 0;
        __syncthreads();
        sh[t] += add;
        __syncthreads();
    }
    if (i < NN) offsets[i] = sh[t] - v;
    if (t == SCAN_BS - 1) blockSums[blockIdx.x] = sh[t];
}

__global__ void scan2_kernel(int* __restrict__ blockSums) {
    __shared__ int sh[1024];
    int t = threadIdx.x;
    int v = (t < SCAN_NB) ? blockSums[t] : 0;
    sh[t] = v;
    __syncthreads();
    for (int ofs = 1; ofs < 1024; ofs <<= 1) {
        int add = (t >= ofs) ? sh[t - ofs] : 0;
        __syncthreads();
        sh[t] += add;
        __syncthreads();
    }
    if (t < SCAN_NB) blockSums[t] = sh[t] - v;
}

__global__ void scan3_kernel(int* __restrict__ offsets,
                             const int* __restrict__ blockSums,
                             int* __restrict__ cursor) {
    int i = blockIdx.x * SCAN_BS + threadIdx.x;
    if (i >= NN) return;
    int o = offsets[i] + blockSums[blockIdx.x];
    offsets[i] = o;
    cursor[i]  = o;
}

__global__ void scatter_kernel(const int* __restrict__ rows,
                               const int* __restrict__ cols,
                               const float* __restrict__ vals,
                               int* __restrict__ cursor,
                               int2* __restrict__ cv) {
    unsigned e = blockIdx.x * blockDim.x + threadIdx.x;
    if (e >= E_NUM) return;
    int r = __ldg(rows + e);
    int pos = atomicAdd(cursor + r, 1);
    cv[pos] = make_int2(__ldg(cols + e), __float_as_int(__ldg(vals + e)));
}

// ---------------------------------------------------------------------------
// CSR SpMM v3: warp per row, 4 edges per iteration, fp16 gather table.
//   lane = g*8 + q : group g in 0..3 handles edge j+g; lane gathers the
//   q-th 16B chunk (8 halves) of the 128B fp16 row. fp32 accumulation.
// Reduction across the 4 groups via shfl_xor(8), shfl_xor(16).
// ---------------------------------------------------------------------------
template <bool WRITE_Y>
__global__ void __launch_bounds__(256)
csr_spmm_kernel(const int* __restrict__ off,
                const int* __restrict__ cnt,
                const int2* __restrict__ cv,
                const uint4* __restrict__ xh,   // fp16 table, 8 uint4 per row
                uint4* __restrict__ yh,         // fp16 out table
                float4* __restrict__ acc) {
    unsigned warpId = (blockIdx.x * blockDim.x + threadIdx.x) >> 5;
    if (warpId >= (unsigned)NN) return;
    const unsigned lane = threadIdx.x & 31u;
    const unsigned g    = lane >> 3;        // edge group 0..3
    const unsigned q    = lane & 7u;        // 16B chunk within the row
    const unsigned row  = warpId;

    int start = __ldg(off + row);
    int n     = __ldg(cnt + row);

    float s0 = 0.f, s1 = 0.f, s2 = 0.f, s3 = 0.f;
    float s4 = 0.f, s5 = 0.f, s6 = 0.f, s7 = 0.f;

    for (int base = 0; base < n; base += 32) {
        int k = base + (int)lane;
        int2 pr = make_int2(0, 0);          // zero-pad: col 0 (hot), val 0
        if (k < n) pr = __ldcs(cv + start + k);
        int m = min(32, n - base);
        #pragma unroll 8
        for (int j = 0; j < m; j += 4) {
            int jj = j + (int)g;
            int   c = __shfl_sync(0xffffffffu, pr.x, jj);
            float v = __int_as_float(__shfl_sync(0xffffffffu, pr.y, jj));
            uint4 hv = __ldg(xh + (size_t)c * 8 + q);
            half2 h0 = *reinterpret_cast<half2*>(&hv.x);
            half2 h1 = *reinterpret_cast<half2*>(&hv.y);
            half2 h2 = *reinterpret_cast<half2*>(&hv.z);
            half2 h3 = *reinterpret_cast<half2*>(&hv.w);
            float2 f0 = __half22float2(h0);
            float2 f1 = __half22float2(h1);
            float2 f2 = __half22float2(h2);
            float2 f3 = __half22float2(h3);
            s0 += v * f0.x; s1 += v * f0.y;
            s2 += v * f1.x; s3 += v * f1.y;
            s4 += v * f2.x; s5 += v * f2.y;
            s6 += v * f3.x; s7 += v * f3.y;
        }
    }

    // reduce across the 4 edge groups (lanes with equal q)
    #define RED(S) S += __shfl_xor_sync(0xffffffffu, S, 8); \
                   S += __shfl_xor_sync(0xffffffffu, S, 16);
    RED(s0) RED(s1) RED(s2) RED(s3) RED(s4) RED(s5) RED(s6) RED(s7)
    #undef RED

    if (lane < 8) {
        if (WRITE_Y) {
            half2 h0 = __floats2half2_rn(s0, s1);
            half2 h1 = __floats2half2_rn(s2, s3);
            half2 h2 = __floats2half2_rn(s4, s5);
            half2 h3 = __floats2half2_rn(s6, s7);
            uint4 packed;
            packed.x = *reinterpret_cast<unsigned*>(&h0);
            packed.y = *reinterpret_cast<unsigned*>(&h1);
            packed.z = *reinterpret_cast<unsigned*>(&h2);
            packed.w = *reinterpret_cast<unsigned*>(&h3);
            yh[(size_t)row * 8 + q] = packed;
        }
        float4* ap = acc + (size_t)row * 16 + q * 2;
        float4 a0 = __ldcs(ap);
        a0.x += s0; a0.y += s1; a0.z += s2; a0.w += s3;
        __stcs(ap, a0);
        float4 a1 = __ldcs(ap + 1);
        a1.x += s4; a1.y += s5; a1.z += s6; a1.w += s7;
        __stcs(ap + 1, a1);
    }
}

extern "C" void kernel_launch(void* const* d_in, const int* in_sizes, int n_in,
                              void* d_out, int out_size) {
    const int*   rows = (const int*)  d_in[0];
    const int*   cols = (const int*)  d_in[1];
    const float* vals = (const float*)d_in[2];
    const float* uEmb = (const float*)d_in[3];
    const float* iEmb = (const float*)d_in[4];
    float* out = (float*)d_out;

    __half* hA;    cudaGetSymbolAddress((void**)&hA,     g_hA);
    __half* hB;    cudaGetSymbolAddress((void**)&hB,     g_hB);
    int2*  cv;     cudaGetSymbolAddress((void**)&cv,     g_cv);
    int*   counts; cudaGetSymbolAddress((void**)&counts, g_counts);
    int*   offs;   cudaGetSymbolAddress((void**)&offs,   g_offsets);
    int*   cursor; cudaGetSymbolAddress((void**)&cursor, g_cursor);
    int*   bsums;  cudaGetSymbolAddress((void**)&bsums,  g_blockSums);

    const int T = 256;
    const int gridDense = (NN * D / 4 + T - 1) / T;
    const int gridE     = (E_NUM + T - 1) / T;
    const int gridSpmm  = (NN * 32 + T - 1) / T;          // warp per row

    // ---- build phase ----
    init_kernel<<<gridDense, T>>>((const float4*)uEmb, (const float4*)iEmb,
                                  (float4*)out, (uint2*)hA, counts);
    hist_kernel<<<gridE, T>>>(rows, counts);
    scan1_kernel<<<SCAN_NB, SCAN_BS>>>(counts, offs, bsums);
    scan2_kernel<<<1, 1024>>>(bsums);
    scan3_kernel<<<SCAN_NB, SCAN_BS>>>(offs, bsums, cursor);
    scatter_kernel<<<gridE, T>>>(rows, cols, vals, cursor, cv);

    // ---- 3 propagation layers (fp16 gather, fp32 acc) ----
    // layer 1: hB = Adj * hA ; out += …
    csr_spmm_kernel<true ><<<gridSpmm, T>>>(offs, counts, cv,
        (const uint4*)hA, (uint4*)hB, (float4*)out);
    // layer 2: hA = Adj * hB ; out += …   (X0 in hA no longer needed)
    csr_spmm_kernel<true ><<<gridSpmm, T>>>(offs, counts, cv,
        (const uint4*)hB, (uint4*)hA, (float4*)out);
    // layer 3: out += Adj * hA
    csr_spmm_kernel<false><<<gridSpmm, T>>>(offs, counts, cv,
        (const uint4*)hA, nullptr, (float4*)out);
}